// round 6
// baseline (speedup 1.0000x reference)
#include <cuda_runtime.h>
#include <cuda_bf16.h>
#include <math.h>
#include <cstdint>

// Problem constants
#define BB   4
#define NN   16384
#define MM   (BB * NN)        // 65536 points
#define HID  128
#define RESO 128
#define R2   (RESO * RESO)
#define NBLK 5
#define LDP  640              // plane row stride (bf16 elems):
                              // [reluH(128) | rawnet(128) | rawpool(128) | relunet(128) | relupool(128)]

// Weight plane offsets (element index into g_wh/g_wl)
#define WOFF_FC0(k)  ((size_t)(k) * 32768)
#define WOFF_WCAT(k) (163840 + (size_t)(k) * 49152)
#define WOFF_FCC     409600
#define WTOTAL       425984

// GEMM smem pipeline geometry
#define STG   40960           // bytes per stage (4 buffers x 10240)
#define BKP   40              // padded row: 40 bf16 = 80 B

// ---------------------------------------------------------------------------
// Scratch
// ---------------------------------------------------------------------------
__device__ int           g_idx[MM];
__device__ __nv_bfloat16 g_Ph[(size_t)MM * LDP];     // 80 MB
__device__ __nv_bfloat16 g_Pl[(size_t)MM * LDP];     // 80 MB
__device__ float         g_FC[(size_t)MM * HID];     // fc_c output, 32 MB
__device__ unsigned      g_bins[(size_t)BB * R2 * HID];
__device__ float         g_cnt[BB * R2];
__device__ __nv_bfloat16 g_wh[WTOTAL];
__device__ __nv_bfloat16 g_wl[WTOTAL];

// ---------------------------------------------------------------------------
// Helpers
// ---------------------------------------------------------------------------
__device__ __forceinline__ uint32_t smem_u32(const void* p) {
    uint32_t a;
    asm("{ .reg .u64 t; cvta.to.shared.u64 t, %1; cvt.u32.u64 %0, t; }"
        : "=r"(a) : "l"(p));
    return a;
}
__device__ __forceinline__ unsigned f_enc(float x) {
    unsigned u = __float_as_uint(x);
    return (u & 0x80000000u) ? ~u : (u | 0x80000000u);
}
__device__ __forceinline__ float f_dec(unsigned u) {
    return (u & 0x80000000u) ? __uint_as_float(u & 0x7FFFFFFFu) : __uint_as_float(~u);
}
__device__ __forceinline__ void split1(float v, __nv_bfloat16& h, __nv_bfloat16& l) {
    h = __float2bfloat16(v);
    l = __float2bfloat16(v - __bfloat162float(h));
}
__device__ __forceinline__ void split2(float a, float b, uint32_t& hp, uint32_t& lp) {
    __nv_bfloat16 ha, la, hb, lb;
    split1(a, ha, la);
    split1(b, hb, lb);
    hp = (uint32_t)__bfloat16_as_ushort(ha) | ((uint32_t)__bfloat16_as_ushort(hb) << 16);
    lp = (uint32_t)__bfloat16_as_ushort(la) | ((uint32_t)__bfloat16_as_ushort(lb) << 16);
}

// mma.sync m16n8k16 bf16 -> f32 accumulate (legal on plain sm_103 target)
__device__ __forceinline__ void mma16816(float* d, const uint32_t* a,
                                         uint32_t b0, uint32_t b1) {
    asm volatile(
        "mma.sync.aligned.m16n8k16.row.col.f32.bf16.bf16.f32 "
        "{%0,%1,%2,%3}, {%4,%5,%6,%7}, {%8,%9}, {%0,%1,%2,%3};"
        : "+f"(d[0]), "+f"(d[1]), "+f"(d[2]), "+f"(d[3])
        : "r"(a[0]), "r"(a[1]), "r"(a[2]), "r"(a[3]), "r"(b0), "r"(b1));
}

// ---------------------------------------------------------------------------
// Weight prep: split all weights into bf16 hi/lo planes
// ---------------------------------------------------------------------------
__global__ void k_wprep(const float* __restrict__ fc0,
                        const float* __restrict__ w1,
                        const float* __restrict__ ws,
                        const float* __restrict__ fcc) {
    int t = blockIdx.x * blockDim.x + threadIdx.x;
    if (t >= WTOTAL) return;
    float v;
    if (t < 163840) {
        v = fc0[t];                               // (NBLK,128,256) contiguous
    } else if (t < 409600) {
        int u = t - 163840;
        int k = u / 49152, r = u % 49152;
        int n = r / 384, c = r % 384;
        if (c < 128) v = w1[((size_t)k * HID + n) * 128 + c];
        else         v = ws[((size_t)k * HID + n) * 256 + (c - 128)];
    } else {
        v = fcc[t - 409600];
    }
    __nv_bfloat16 h, l;
    split1(v, h, l);
    g_wh[t] = h;
    g_wl[t] = l;
}

// ---------------------------------------------------------------------------
// fc_pos: x_j -> raw split at col 128+j, relu split at col 384+j; bin idx
// ---------------------------------------------------------------------------
__global__ void k_pos(const float* __restrict__ pts,
                      const float* __restrict__ w,
                      const float* __restrict__ b) {
    int m = blockIdx.x;
    int j = threadIdx.x;                 // 0..255
    float p0 = pts[(size_t)m * 3 + 0];
    float p1 = pts[(size_t)m * 3 + 1];
    float p2 = pts[(size_t)m * 3 + 2];
    float v = b[j] + p0 * w[j * 3 + 0] + p1 * w[j * 3 + 1] + p2 * w[j * 3 + 2];
    size_t base = (size_t)m * LDP;
    __nv_bfloat16 h, l;
    split1(v, h, l);
    g_Ph[base + 128 + j] = h;
    g_Pl[base + 128 + j] = l;
    float r = fmaxf(v, 0.f);
    split1(r, h, l);
    g_Ph[base + 384 + j] = h;
    g_Pl[base + 384 + j] = l;
    if (j == 0) {
        int gx = (int)(p0 * (float)RESO);
        int gy = (int)(p1 * (float)RESO);
        gx = min(max(gx, 0), RESO - 1);
        gy = min(max(gy, 0), RESO - 1);
        g_idx[m] = gx + RESO * gy;
    }
}

// ---------------------------------------------------------------------------
// Pipelined mma.sync GEMM: C[M x 128] = A[M x K] @ W^T + bias
// A = pre-split bf16 planes (cols a_col0..a_col0+K), W = pre-split planes.
// 2-stage cp.async double buffer; BK=32; 8 warps (4x2); 3-MMA hi/lo combos.
// mode 0: write relu(C) split -> col 0       (GEMM1: H)
// mode 1: write C split -> col 128 and relu(C) split -> col 384 (GEMM2: net)
// mode 2: write C f32 -> g_FC                (fc_c)
// ---------------------------------------------------------------------------
__global__ void __launch_bounds__(256, 2) k_gemm_mma(
    int a_col0, size_t woff, int K, const float* __restrict__ bias, int mode)
{
    extern __shared__ char dsm[];
    uint32_t sbase = smem_u32(dsm);
    float* bias_s = (float*)(dsm + 2 * STG);

    int tid = threadIdx.x;
    int wid = tid >> 5;
    int lid = tid & 31;
    int m0  = blockIdx.x * 128;
    int warp_m = wid & 3;
    int warp_n = wid >> 2;
    int g  = lid >> 2;
    int tg = lid & 3;

    if (tid < 128) bias_s[tid] = bias[tid];

    // Per-thread cp.async source pointers (advance 64 B per chunk) + smem offs
    uint64_t gptr[8];
    uint32_t soff[8];
    {
        int f   = tid;
        int row = f >> 3, rem = f & 7, pl = rem >> 2, seg = rem & 3;
        // 4 A segments (i strides +256 -> +32 rows)
        #pragma unroll
        for (int i = 0; i < 4; i++) {
            int r2 = row + (i << 5);
            const __nv_bfloat16* gp = pl ? g_Pl : g_Ph;
            gptr[i] = (uint64_t)(gp + (size_t)(m0 + r2) * LDP + a_col0 + seg * 8);
            soff[i] = pl * 10240 + r2 * 80 + seg * 16;
        }
        // 4 W segments
        #pragma unroll
        for (int i = 0; i < 4; i++) {
            int r2 = row + (i << 5);
            const __nv_bfloat16* gp = pl ? g_wl : g_wh;
            gptr[4 + i] = (uint64_t)(gp + woff + (size_t)r2 * K + seg * 8);
            soff[4 + i] = 20480 + pl * 10240 + r2 * 80 + seg * 16;
        }
    }

    auto issue = [&](int c, int s) {
        uint32_t sb = sbase + s * STG;
        uint64_t adv = (uint64_t)(c << 6);     // c * 64 bytes (32 bf16 cols)
        #pragma unroll
        for (int i = 0; i < 8; i++) {
            asm volatile("cp.async.cg.shared.global [%0], [%1], 16;"
                         :: "r"(sb + soff[i]), "l"(gptr[i] + adv) : "memory");
        }
        asm volatile("cp.async.commit_group;" ::: "memory");
    };

    float acc[2][8][4];
    #pragma unroll
    for (int mt = 0; mt < 2; mt++)
        #pragma unroll
        for (int nt = 0; nt < 8; nt++)
            #pragma unroll
            for (int r = 0; r < 4; r++) acc[mt][nt][r] = 0.f;

    const int nchunks = K >> 5;
    issue(0, 0);

    for (int c = 0; c < nchunks; c++) {
        if (c + 1 < nchunks) {
            issue(c + 1, (c + 1) & 1);
            asm volatile("cp.async.wait_group 1;" ::: "memory");
        } else {
            asm volatile("cp.async.wait_group 0;" ::: "memory");
        }
        __syncthreads();

        const char* sp = dsm + (c & 1) * STG;
        const uint32_t* A32h = (const uint32_t*)(sp);
        const uint32_t* A32l = (const uint32_t*)(sp + 10240);
        const uint32_t* W32h = (const uint32_t*)(sp + 20480);
        const uint32_t* W32l = (const uint32_t*)(sp + 30720);

        #pragma unroll
        for (int ks = 0; ks < 2; ks++) {
            int kb = (ks << 3) + tg;
            uint32_t ah[2][4], al[2][4];
            #pragma unroll
            for (int mt = 0; mt < 2; mt++) {
                int r0 = (warp_m << 5) + (mt << 4) + g;
                int b0 = r0 * (BKP / 2) + kb;
                int b1 = b0 + 8 * (BKP / 2);
                ah[mt][0] = A32h[b0];     ah[mt][1] = A32h[b1];
                ah[mt][2] = A32h[b0 + 4]; ah[mt][3] = A32h[b1 + 4];
                al[mt][0] = A32l[b0];     al[mt][1] = A32l[b1];
                al[mt][2] = A32l[b0 + 4]; al[mt][3] = A32l[b1 + 4];
            }
            #pragma unroll
            for (int nt = 0; nt < 8; nt++) {
                int n  = (warp_n << 6) + (nt << 3) + g;
                int bb = n * (BKP / 2) + kb;
                uint32_t bh0 = W32h[bb], bh1 = W32h[bb + 4];
                uint32_t bl0 = W32l[bb], bl1 = W32l[bb + 4];
                #pragma unroll
                for (int mt = 0; mt < 2; mt++) {
                    mma16816(acc[mt][nt], ah[mt], bh0, bh1);
                    mma16816(acc[mt][nt], ah[mt], bl0, bl1);
                    mma16816(acc[mt][nt], al[mt], bh0, bh1);
                }
            }
        }
        __syncthreads();
    }

    // Epilogue
    #pragma unroll
    for (int mt = 0; mt < 2; mt++) {
        int row0 = m0 + (warp_m << 5) + (mt << 4) + g;
        #pragma unroll
        for (int nt = 0; nt < 8; nt++) {
            int colL = (warp_n << 6) + (nt << 3) + (tg << 1);
            float b0 = bias_s[colL], b1 = bias_s[colL + 1];
            float v0 = acc[mt][nt][0] + b0, v1 = acc[mt][nt][1] + b1;  // row0
            float v2 = acc[mt][nt][2] + b0, v3 = acc[mt][nt][3] + b1;  // row0+8
            if (mode == 2) {
                *(float2*)(g_FC + (size_t)row0 * HID + colL) = make_float2(v0, v1);
                *(float2*)(g_FC + (size_t)(row0 + 8) * HID + colL) = make_float2(v2, v3);
            } else {
                size_t p0 = (size_t)row0 * LDP;
                size_t p1 = (size_t)(row0 + 8) * LDP;
                uint32_t hp, lp;
                if (mode == 1) {   // raw net -> col 128
                    split2(v0, v1, hp, lp);
                    *(uint32_t*)(g_Ph + p0 + 128 + colL) = hp;
                    *(uint32_t*)(g_Pl + p0 + 128 + colL) = lp;
                    split2(v2, v3, hp, lp);
                    *(uint32_t*)(g_Ph + p1 + 128 + colL) = hp;
                    *(uint32_t*)(g_Pl + p1 + 128 + colL) = lp;
                }
                int rc = (mode == 1) ? 384 : 0;  // relu dest
                split2(fmaxf(v0, 0.f), fmaxf(v1, 0.f), hp, lp);
                *(uint32_t*)(g_Ph + p0 + rc + colL) = hp;
                *(uint32_t*)(g_Pl + p0 + rc + colL) = lp;
                split2(fmaxf(v2, 0.f), fmaxf(v3, 0.f), hp, lp);
                *(uint32_t*)(g_Ph + p1 + rc + colL) = hp;
                *(uint32_t*)(g_Pl + p1 + rc + colL) = lp;
            }
        }
    }
}

// ---------------------------------------------------------------------------
// Pool / scatter kernels
// ---------------------------------------------------------------------------
__global__ void k_zero() {
    size_t t = (size_t)blockIdx.x * blockDim.x + threadIdx.x;
    const size_t nb = (size_t)BB * R2 * HID;
    if (t < nb) g_bins[t] = 0u;
    if (t < (size_t)BB * R2) g_cnt[t] = 0.f;
}

// raw net at plane col 128+f -> scatter-max
__global__ void k_smax() {
    int t = blockIdx.x * blockDim.x + threadIdx.x;
    int m = t >> 7, f = t & 127;
    int b = m >> 14;
    size_t base = (size_t)m * LDP + 128 + f;
    float v = __bfloat162float(g_Ph[base]) + __bfloat162float(g_Pl[base]);
    unsigned* dst = &g_bins[((size_t)(b << 14) + g_idx[m]) * HID + f];
    atomicMax(dst, f_enc(v));
}

// gather pooled -> raw split at col 256+f, relu split at col 512+f
__global__ void k_gather() {
    int t = blockIdx.x * blockDim.x + threadIdx.x;
    int m = t >> 7, f = t & 127;
    int b = m >> 14;
    float v = f_dec(g_bins[((size_t)(b << 14) + g_idx[m]) * HID + f]);
    size_t base = (size_t)m * LDP;
    __nv_bfloat16 h, l;
    split1(v, h, l);
    g_Ph[base + 256 + f] = h;
    g_Pl[base + 256 + f] = l;
    float r = fmaxf(v, 0.f);
    split1(r, h, l);
    g_Ph[base + 512 + f] = h;
    g_Pl[base + 512 + f] = l;
}

__global__ void k_ssum() {
    int t = blockIdx.x * blockDim.x + threadIdx.x;
    int m = t >> 7, f = t & 127;
    int b = m >> 14;
    float v = g_FC[(size_t)m * HID + f];
    float* sums = (float*)g_bins;
    atomicAdd(&sums[((size_t)(b << 14) + g_idx[m]) * HID + f], v);
    if (f == 0) atomicAdd(&g_cnt[(b << 14) + g_idx[m]], 1.0f);
}

__global__ void k_final(float* __restrict__ out) {
    __shared__ float s[32][33];
    __shared__ float sc[32];
    int b    = blockIdx.z;
    int bin0 = blockIdx.x * 32;
    int c0   = blockIdx.y * 32;
    const float* sums = (const float*)g_bins;

    #pragma unroll
    for (int i = 0; i < 4; i++) {
        int binl = threadIdx.y + i * 8;
        s[binl][threadIdx.x] =
            sums[((size_t)(b * R2 + bin0 + binl)) * HID + c0 + threadIdx.x];
    }
    if (threadIdx.y == 0)
        sc[threadIdx.x] = fmaxf(g_cnt[b * R2 + bin0 + threadIdx.x], 1.0f);
    __syncthreads();

    #pragma unroll
    for (int i = 0; i < 4; i++) {
        int c = c0 + threadIdx.y + i * 8;
        out[((size_t)(b * HID + c)) * R2 + bin0 + threadIdx.x] =
            s[threadIdx.x][threadIdx.y + i * 8] / sc[threadIdx.x];
    }
}

// ---------------------------------------------------------------------------
// Launch
// ---------------------------------------------------------------------------
extern "C" void kernel_launch(void* const* d_in, const int* in_sizes, int n_in,
                              void* d_out, int out_size) {
    const float* points    = (const float*)d_in[0];
    const float* fc_pos_w  = (const float*)d_in[1];
    const float* fc_pos_b  = (const float*)d_in[2];
    const float* blk_fc0_w = (const float*)d_in[3];
    const float* blk_fc0_b = (const float*)d_in[4];
    const float* blk_fc1_w = (const float*)d_in[5];
    const float* blk_fc1_b = (const float*)d_in[6];
    const float* blk_sc_w  = (const float*)d_in[7];
    const float* fc_c_w    = (const float*)d_in[8];
    const float* fc_c_b    = (const float*)d_in[9];
    float* out = (float*)d_out;

    const int GEMM_BLOCKS = MM / 128;          // 512
    const int PF_BLOCKS   = (MM * HID) / 256;  // 32768
    const int SMEM_SZ     = 2 * STG + 512;     // 82432 B

    cudaFuncSetAttribute(k_gemm_mma, cudaFuncAttributeMaxDynamicSharedMemorySize, SMEM_SZ);

    // Weight hi/lo split prep
    k_wprep<<<(WTOTAL + 255) / 256, 256>>>(blk_fc0_w, blk_fc1_w, blk_sc_w, fc_c_w);

    // fc_pos -> planes cols [128,384) raw, [384,640) relu; bin indices
    k_pos<<<MM, 256>>>(points, fc_pos_w, fc_pos_b);

    // Block 0: GEMM1 reads relu-x [384,640) K=256; GEMM2 reads [0,384) K=384
    k_gemm_mma<<<GEMM_BLOCKS, 256, SMEM_SZ>>>(384, WOFF_FC0(0), 256, blk_fc0_b, 0);
    k_gemm_mma<<<GEMM_BLOCKS, 256, SMEM_SZ>>>(0, WOFF_WCAT(0), 384, blk_fc1_b, 1);

    // Blocks 1..4: pool(max) -> gather -> resblock
    for (int k = 1; k < NBLK; k++) {
        k_zero<<<32768, 256>>>();
        k_smax<<<PF_BLOCKS, 256>>>();
        k_gather<<<PF_BLOCKS, 256>>>();
        k_gemm_mma<<<GEMM_BLOCKS, 256, SMEM_SZ>>>(384, WOFF_FC0(k), 256,
                                                  blk_fc0_b + k * HID, 0);
        k_gemm_mma<<<GEMM_BLOCKS, 256, SMEM_SZ>>>(0, WOFF_WCAT(k), 384,
                                                  blk_fc1_b + k * HID, 1);
    }

    // fc_c: reads relu-net [384,512) K=128 -> g_FC
    k_gemm_mma<<<GEMM_BLOCKS, 256, SMEM_SZ>>>(384, WOFF_FCC, 128, fc_c_b, 2);

    // scatter_mean + transposed plane write
    k_zero<<<32768, 256>>>();
    k_ssum<<<PF_BLOCKS, 256>>>();
    dim3 fgrid(R2 / 32, HID / 32, BB);
    dim3 fblk(32, 8);
    k_final<<<fgrid, fblk>>>(out);
}

// round 8
// speedup vs baseline: 1.0950x; 1.0950x over previous
#include <cuda_runtime.h>
#include <cuda_bf16.h>
#include <math.h>
#include <cstdint>

// Problem constants
#define BB   4
#define NN   16384
#define MM   (BB * NN)        // 65536 points total
#define HID  128
#define RESO 128
#define R2   (RESO * RESO)
#define NBLK 5
#define LDXH 384              // row buffer: [H(128) | net(128) | pooled(128)]

// Weight plane offsets (element index into g_wh/g_wl)
#define WOFF_FC0(k)  ((size_t)(k) * 32768)
#define WOFF_WCAT(k) (163840 + (size_t)(k) * 49152)
#define WOFF_FCC     409600
#define WTOTAL       425984

// GEMM smem pipeline geometry (per stage):
//   A f32 : 128 rows x 40 f32 pitch  = 20480 B  (32 cols used)
//   W hi  : 128 rows x 40 bf16 pitch = 10240 B  (32 cols used)
//   W lo  : 10240 B
#define STG 40960

// ---------------------------------------------------------------------------
// Scratch
// ---------------------------------------------------------------------------
__device__ int           g_idx[MM];
__device__ float         g_XH[(size_t)MM * LDXH];          // ~100 MB (L2-resident)
__device__ unsigned      g_bins[(size_t)BB * R2 * HID];
__device__ float         g_cnt[BB * R2];
__device__ __nv_bfloat16 g_wh[WTOTAL];
__device__ __nv_bfloat16 g_wl[WTOTAL];

// ---------------------------------------------------------------------------
// Helpers
// ---------------------------------------------------------------------------
__device__ __forceinline__ uint32_t smem_u32(const void* p) {
    uint32_t a;
    asm("{ .reg .u64 t; cvta.to.shared.u64 t, %1; cvt.u32.u64 %0, t; }"
        : "=r"(a) : "l"(p));
    return a;
}
__device__ __forceinline__ unsigned f_enc(float x) {
    unsigned u = __float_as_uint(x);
    return (u & 0x80000000u) ? ~u : (u | 0x80000000u);
}
__device__ __forceinline__ float f_dec(unsigned u) {
    return (u & 0x80000000u) ? __uint_as_float(u & 0x7FFFFFFFu) : __uint_as_float(~u);
}
__device__ __forceinline__ void split2(float a, float b, uint32_t& hp, uint32_t& lp) {
    __nv_bfloat16 ha = __float2bfloat16(a), hb = __float2bfloat16(b);
    float ra = a - __bfloat162float(ha);
    float rb = b - __bfloat162float(hb);
    __nv_bfloat16 la = __float2bfloat16(ra), lb = __float2bfloat16(rb);
    hp = (uint32_t)__bfloat16_as_ushort(ha) | ((uint32_t)__bfloat16_as_ushort(hb) << 16);
    lp = (uint32_t)__bfloat16_as_ushort(la) | ((uint32_t)__bfloat16_as_ushort(lb) << 16);
}

// mma.sync m16n8k16 bf16 -> f32 accumulate
__device__ __forceinline__ void mma16816(float* d, const uint32_t* a,
                                         uint32_t b0, uint32_t b1) {
    asm volatile(
        "mma.sync.aligned.m16n8k16.row.col.f32.bf16.bf16.f32 "
        "{%0,%1,%2,%3}, {%4,%5,%6,%7}, {%8,%9}, {%0,%1,%2,%3};"
        : "+f"(d[0]), "+f"(d[1]), "+f"(d[2]), "+f"(d[3])
        : "r"(a[0]), "r"(a[1]), "r"(a[2]), "r"(a[3]), "r"(b0), "r"(b1));
}

// ---------------------------------------------------------------------------
// Weight prep: split all weights into bf16 hi/lo planes
// ---------------------------------------------------------------------------
__global__ void k_wprep(const float* __restrict__ fc0,
                        const float* __restrict__ w1,
                        const float* __restrict__ ws,
                        const float* __restrict__ fcc) {
    int t = blockIdx.x * blockDim.x + threadIdx.x;
    if (t >= WTOTAL) return;
    float v;
    if (t < 163840) {
        v = fc0[t];                               // (NBLK,128,256) contiguous
    } else if (t < 409600) {
        int u = t - 163840;
        int k = u / 49152, r = u % 49152;
        int n = r / 384, c = r % 384;
        if (c < 128) v = w1[((size_t)k * HID + n) * 128 + c];
        else         v = ws[((size_t)k * HID + n) * 256 + (c - 128)];
    } else {
        v = fcc[t - 409600];
    }
    __nv_bfloat16 hi = __float2bfloat16(v);
    float lo = v - __bfloat162float(hi);
    g_wh[t] = hi;
    g_wl[t] = __float2bfloat16(lo);
}

// ---------------------------------------------------------------------------
// fc_pos + bin index
// ---------------------------------------------------------------------------
__global__ void k_pos(const float* __restrict__ pts,
                      const float* __restrict__ w,
                      const float* __restrict__ b) {
    int m = blockIdx.x;
    int j = threadIdx.x;
    float p0 = pts[(size_t)m * 3 + 0];
    float p1 = pts[(size_t)m * 3 + 1];
    float p2 = pts[(size_t)m * 3 + 2];
    float v = b[j] + p0 * w[j * 3 + 0] + p1 * w[j * 3 + 1] + p2 * w[j * 3 + 2];
    g_XH[(size_t)m * LDXH + 128 + j] = v;
    if (j == 0) {
        int gx = (int)(p0 * (float)RESO);
        int gy = (int)(p1 * (float)RESO);
        gx = min(max(gx, 0), RESO - 1);
        gy = min(max(gy, 0), RESO - 1);
        g_idx[m] = gx + RESO * gy;
    }
}

// ---------------------------------------------------------------------------
// Pipelined mma.sync GEMM: C[M x 128] = act(A[M x K]) @ W^T + bias
// A staged as RAW f32 via cp.async (2-stage double buffer); relu + hi/lo
// split happen at fragment-load time (LDS.64 f32 -> split2 -> frag regs).
// W pre-split bf16 hi/lo planes staged via cp.async.
// 8 warps (4 M x 2 N), BK=32, 3-MMA hi/lo combos. Output f32 -> g_XH.
// ---------------------------------------------------------------------------
__global__ void __launch_bounds__(256, 2) k_gemm_mma(
    int a_col0, size_t woff, int K, int relu_limit,
    const float* __restrict__ bias, int c_col0)
{
    extern __shared__ char dsm[];
    uint32_t sbase = smem_u32(dsm);
    float* bias_s = (float*)(dsm + 2 * STG);

    int tid = threadIdx.x;
    int wid = tid >> 5;
    int lid = tid & 31;
    int m0  = blockIdx.x * 128;
    int warp_m = wid & 3;
    int warp_n = wid >> 2;
    int g  = lid >> 2;
    int tg = lid & 3;

    if (tid < 128) bias_s[tid] = bias[tid];

    // Per-thread cp.async sources + smem offsets (8 x 16B per chunk)
    uint64_t gA[4]; uint32_t sA[4];
    uint64_t gW[4]; uint32_t sW[4];
    {
        #pragma unroll
        for (int i = 0; i < 4; i++) {
            int idx = tid + (i << 8);        // 0..1023
            int row = idx >> 3, seg = idx & 7;
            gA[i] = (uint64_t)(g_XH + (size_t)(m0 + row) * LDXH + a_col0 + seg * 4);
            sA[i] = row * 160 + seg * 16;
        }
        #pragma unroll
        for (int i = 0; i < 4; i++) {
            int idx = tid + (i << 8);        // 0..1023
            int pl = idx >> 9, rem = idx & 511;
            int row = rem >> 2, seg = rem & 3;
            const __nv_bfloat16* gp = pl ? g_wl : g_wh;
            gW[i] = (uint64_t)(gp + woff + (size_t)row * K + seg * 8);
            sW[i] = 20480 + pl * 10240 + row * 80 + seg * 16;
        }
    }

    auto issue = [&](int c, int s) {
        uint32_t sb = sbase + s * STG;
        uint64_t advA = (uint64_t)(c << 7);   // 32 f32  = 128 B
        uint64_t advW = (uint64_t)(c << 6);   // 32 bf16 = 64 B
        #pragma unroll
        for (int i = 0; i < 4; i++)
            asm volatile("cp.async.cg.shared.global [%0], [%1], 16;"
                         :: "r"(sb + sA[i]), "l"(gA[i] + advA) : "memory");
        #pragma unroll
        for (int i = 0; i < 4; i++)
            asm volatile("cp.async.cg.shared.global [%0], [%1], 16;"
                         :: "r"(sb + sW[i]), "l"(gW[i] + advW) : "memory");
        asm volatile("cp.async.commit_group;" ::: "memory");
    };

    float acc[2][8][4];
    #pragma unroll
    for (int mt = 0; mt < 2; mt++)
        #pragma unroll
        for (int nt = 0; nt < 8; nt++)
            #pragma unroll
            for (int r = 0; r < 4; r++) acc[mt][nt][r] = 0.f;

    const int nchunks = K >> 5;
    issue(0, 0);

    for (int c = 0; c < nchunks; c++) {
        if (c + 1 < nchunks) {
            issue(c + 1, (c + 1) & 1);
            asm volatile("cp.async.wait_group 1;" ::: "memory");
        } else {
            asm volatile("cp.async.wait_group 0;" ::: "memory");
        }
        __syncthreads();

        const char* sp = dsm + (c & 1) * STG;
        const float*    Af   = (const float*)sp;
        const uint32_t* W32h = (const uint32_t*)(sp + 20480);
        const uint32_t* W32l = (const uint32_t*)(sp + 30720);
        bool dorelu = ((c << 5) < relu_limit);   // relu_limit mult of 32 -> uniform

        #pragma unroll
        for (int ks = 0; ks < 2; ks++) {
            int col0 = (ks << 4) + (tg << 1);
            int kb   = (ks << 3) + tg;
            uint32_t ah[2][4], al[2][4];
            #pragma unroll
            for (int mt = 0; mt < 2; mt++) {
                int r0 = (warp_m << 5) + (mt << 4) + g;
                float2 v0 = *(const float2*)(Af + r0 * 40 + col0);
                float2 v1 = *(const float2*)(Af + (r0 + 8) * 40 + col0);
                float2 v2 = *(const float2*)(Af + r0 * 40 + col0 + 8);
                float2 v3 = *(const float2*)(Af + (r0 + 8) * 40 + col0 + 8);
                if (dorelu) {
                    v0.x = fmaxf(v0.x, 0.f); v0.y = fmaxf(v0.y, 0.f);
                    v1.x = fmaxf(v1.x, 0.f); v1.y = fmaxf(v1.y, 0.f);
                    v2.x = fmaxf(v2.x, 0.f); v2.y = fmaxf(v2.y, 0.f);
                    v3.x = fmaxf(v3.x, 0.f); v3.y = fmaxf(v3.y, 0.f);
                }
                split2(v0.x, v0.y, ah[mt][0], al[mt][0]);
                split2(v1.x, v1.y, ah[mt][1], al[mt][1]);
                split2(v2.x, v2.y, ah[mt][2], al[mt][2]);
                split2(v3.x, v3.y, ah[mt][3], al[mt][3]);
            }
            #pragma unroll
            for (int nt = 0; nt < 8; nt++) {
                int n  = (warp_n << 6) + (nt << 3) + g;
                int bb = n * 20 + kb;
                uint32_t bh0 = W32h[bb], bh1 = W32h[bb + 4];
                uint32_t bl0 = W32l[bb], bl1 = W32l[bb + 4];
                #pragma unroll
                for (int mt = 0; mt < 2; mt++) {
                    mma16816(acc[mt][nt], ah[mt], bh0, bh1);
                    mma16816(acc[mt][nt], ah[mt], bl0, bl1);
                    mma16816(acc[mt][nt], al[mt], bh0, bh1);
                }
            }
        }
        __syncthreads();
    }

    // Epilogue: d0,d1 -> row g cols 2tg..; d2,d3 -> row g+8
    #pragma unroll
    for (int mt = 0; mt < 2; mt++) {
        int row0 = m0 + (warp_m << 5) + (mt << 4) + g;
        #pragma unroll
        for (int nt = 0; nt < 8; nt++) {
            int colL = (warp_n << 6) + (nt << 3) + (tg << 1);
            float b0 = bias_s[colL], b1 = bias_s[colL + 1];
            float2 v0 = make_float2(acc[mt][nt][0] + b0, acc[mt][nt][1] + b1);
            float2 v1 = make_float2(acc[mt][nt][2] + b0, acc[mt][nt][3] + b1);
            *(float2*)(g_XH + (size_t)row0 * LDXH + c_col0 + colL) = v0;
            *(float2*)(g_XH + (size_t)(row0 + 8) * LDXH + c_col0 + colL) = v1;
        }
    }
}

// ---------------------------------------------------------------------------
// Pool / scatter kernels
// ---------------------------------------------------------------------------
__global__ void k_zero() {
    size_t t = (size_t)blockIdx.x * blockDim.x + threadIdx.x;
    const size_t nb = (size_t)BB * R2 * HID;
    if (t < nb) g_bins[t] = 0u;
    if (t < (size_t)BB * R2) g_cnt[t] = 0.f;
}

__global__ void k_smax() {
    int t = blockIdx.x * blockDim.x + threadIdx.x;
    int m = t >> 7, f = t & 127;
    int b = m >> 14;
    float v = g_XH[(size_t)m * LDXH + 128 + f];
    unsigned* dst = &g_bins[((size_t)(b << 14) + g_idx[m]) * HID + f];
    atomicMax(dst, f_enc(v));
}

__global__ void k_gather() {
    int t = blockIdx.x * blockDim.x + threadIdx.x;
    int m = t >> 7, f = t & 127;
    int b = m >> 14;
    unsigned u = g_bins[((size_t)(b << 14) + g_idx[m]) * HID + f];
    g_XH[(size_t)m * LDXH + 256 + f] = f_dec(u);
}

__global__ void k_ssum() {
    int t = blockIdx.x * blockDim.x + threadIdx.x;
    int m = t >> 7, f = t & 127;
    int b = m >> 14;
    float v = g_XH[(size_t)m * LDXH + f];
    float* sums = (float*)g_bins;
    atomicAdd(&sums[((size_t)(b << 14) + g_idx[m]) * HID + f], v);
    if (f == 0) atomicAdd(&g_cnt[(b << 14) + g_idx[m]], 1.0f);
}

__global__ void k_final(float* __restrict__ out) {
    __shared__ float s[32][33];
    __shared__ float sc[32];
    int b    = blockIdx.z;
    int bin0 = blockIdx.x * 32;
    int c0   = blockIdx.y * 32;
    const float* sums = (const float*)g_bins;

    #pragma unroll
    for (int i = 0; i < 4; i++) {
        int binl = threadIdx.y + i * 8;
        s[binl][threadIdx.x] =
            sums[((size_t)(b * R2 + bin0 + binl)) * HID + c0 + threadIdx.x];
    }
    if (threadIdx.y == 0)
        sc[threadIdx.x] = fmaxf(g_cnt[b * R2 + bin0 + threadIdx.x], 1.0f);
    __syncthreads();

    #pragma unroll
    for (int i = 0; i < 4; i++) {
        int c = c0 + threadIdx.y + i * 8;
        out[((size_t)(b * HID + c)) * R2 + bin0 + threadIdx.x] =
            s[threadIdx.x][threadIdx.y + i * 8] / sc[threadIdx.x];
    }
}

// ---------------------------------------------------------------------------
// Launch
// ---------------------------------------------------------------------------
extern "C" void kernel_launch(void* const* d_in, const int* in_sizes, int n_in,
                              void* d_out, int out_size) {
    const float* points    = (const float*)d_in[0];
    const float* fc_pos_w  = (const float*)d_in[1];
    const float* fc_pos_b  = (const float*)d_in[2];
    const float* blk_fc0_w = (const float*)d_in[3];
    const float* blk_fc0_b = (const float*)d_in[4];
    const float* blk_fc1_w = (const float*)d_in[5];
    const float* blk_fc1_b = (const float*)d_in[6];
    const float* blk_sc_w  = (const float*)d_in[7];
    const float* fc_c_w    = (const float*)d_in[8];
    const float* fc_c_b    = (const float*)d_in[9];
    float* out = (float*)d_out;

    const int GEMM_BLOCKS = MM / 128;          // 512
    const int PF_BLOCKS   = (MM * HID) / 256;  // 32768
    const int SMEM_SZ     = 2 * STG + 512;     // 82432 B

    cudaFuncSetAttribute(k_gemm_mma, cudaFuncAttributeMaxDynamicSharedMemorySize, SMEM_SZ);

    // Weight hi/lo split prep
    k_wprep<<<(WTOTAL + 255) / 256, 256>>>(blk_fc0_w, blk_fc1_w, blk_sc_w, fc_c_w);

    // fc_pos -> XH[:,128:384] raw f32, bin indices
    k_pos<<<MM, 256>>>(points, fc_pos_w, fc_pos_b);

    // Block 0: H = relu(x-ext)@W0^T ; net = [relu(H)|x-ext]@Wcat^T
    k_gemm_mma<<<GEMM_BLOCKS, 256, SMEM_SZ>>>(128, WOFF_FC0(0), 256, 256, blk_fc0_b, 0);
    k_gemm_mma<<<GEMM_BLOCKS, 256, SMEM_SZ>>>(0, WOFF_WCAT(0), 384, 128, blk_fc1_b, 128);

    // Blocks 1..4: pool(max) -> gather -> resblock
    for (int k = 1; k < NBLK; k++) {
        k_zero<<<32768, 256>>>();
        k_smax<<<PF_BLOCKS, 256>>>();
        k_gather<<<PF_BLOCKS, 256>>>();
        k_gemm_mma<<<GEMM_BLOCKS, 256, SMEM_SZ>>>(128, WOFF_FC0(k), 256, 256,
                                                  blk_fc0_b + k * HID, 0);
        k_gemm_mma<<<GEMM_BLOCKS, 256, SMEM_SZ>>>(0, WOFF_WCAT(k), 384, 128,
                                                  blk_fc1_b + k * HID, 128);
    }

    // fc_c: relu(net) @ fc_c_w^T -> XH[:,0:128]
    k_gemm_mma<<<GEMM_BLOCKS, 256, SMEM_SZ>>>(128, WOFF_FCC, 128, 128, fc_c_b, 0);

    // scatter_mean + transposed plane write
    k_zero<<<32768, 256>>>();
    k_ssum<<<PF_BLOCKS, 256>>>();
    dim3 fgrid(R2 / 32, HID / 32, BB);
    dim3 fblk(32, 8);
    k_final<<<fgrid, fblk>>>(out);
}

// round 9
// speedup vs baseline: 1.2556x; 1.1467x over previous
#include <cuda_runtime.h>
#include <cuda_bf16.h>
#include <math.h>
#include <cstdint>

// Problem constants
#define BB   4
#define NN   16384
#define MM   (BB * NN)        // 65536 points total
#define HID  128
#define RESO 128
#define R2   (RESO * RESO)
#define NBLK 5
#define LDXH 384              // row buffer: [H(128) | net(128) | (unused 128)]

// Weight plane offsets (element index into g_wh/g_wl)
#define WOFF_FC0(k)  ((size_t)(k) * 32768)
#define WOFF_WCAT(k) (163840 + (size_t)(k) * 49152)
#define WOFF_FCC     409600
#define WTOTAL       425984

// GEMM smem stage: A f32 pitch40 (20480 B) + W hi/lo bf16 pitch40 (2x10240 B)
#define STG 40960

// ---------------------------------------------------------------------------
// Scratch
// ---------------------------------------------------------------------------
__device__ int           g_idx[MM];
__device__ float         g_XH[(size_t)MM * LDXH];          // ~100 MB (L2-resident)
__device__ unsigned      g_bins0[(size_t)BB * R2 * HID];   // 33.5 MB
__device__ unsigned      g_bins1[(size_t)BB * R2 * HID];   // 33.5 MB
__device__ float         g_cnt[BB * R2];
__device__ __nv_bfloat16 g_wh[WTOTAL];
__device__ __nv_bfloat16 g_wl[WTOTAL];

// ---------------------------------------------------------------------------
// Helpers
// ---------------------------------------------------------------------------
__device__ __forceinline__ uint32_t smem_u32(const void* p) {
    uint32_t a;
    asm("{ .reg .u64 t; cvta.to.shared.u64 t, %1; cvt.u32.u64 %0, t; }"
        : "=r"(a) : "l"(p));
    return a;
}
__device__ __forceinline__ unsigned f_enc(float x) {
    unsigned u = __float_as_uint(x);
    return (u & 0x80000000u) ? ~u : (u | 0x80000000u);
}
__device__ __forceinline__ float f_dec(unsigned u) {
    return (u & 0x80000000u) ? __uint_as_float(u & 0x7FFFFFFFu) : __uint_as_float(~u);
}
// A-element conversion: enc = value is f_enc-coded (from bins), relu = apply relu
__device__ __forceinline__ float cvtA(uint32_t u, bool enc, bool relu) {
    if (!enc) {
        float f = __uint_as_float(u);
        return relu ? fmaxf(f, 0.f) : f;
    }
    if (relu) return (u > 0x80000000u) ? __uint_as_float(u & 0x7FFFFFFFu) : 0.f;
    return f_dec(u);
}
__device__ __forceinline__ void split2(float a, float b, uint32_t& hp, uint32_t& lp) {
    __nv_bfloat16 ha = __float2bfloat16(a), hb = __float2bfloat16(b);
    float ra = a - __bfloat162float(ha);
    float rb = b - __bfloat162float(hb);
    __nv_bfloat16 la = __float2bfloat16(ra), lb = __float2bfloat16(rb);
    hp = (uint32_t)__bfloat16_as_ushort(ha) | ((uint32_t)__bfloat16_as_ushort(hb) << 16);
    lp = (uint32_t)__bfloat16_as_ushort(la) | ((uint32_t)__bfloat16_as_ushort(lb) << 16);
}

// mma.sync m16n8k16 bf16 -> f32 accumulate
__device__ __forceinline__ void mma16816(float* d, const uint32_t* a,
                                         uint32_t b0, uint32_t b1) {
    asm volatile(
        "mma.sync.aligned.m16n8k16.row.col.f32.bf16.bf16.f32 "
        "{%0,%1,%2,%3}, {%4,%5,%6,%7}, {%8,%9}, {%0,%1,%2,%3};"
        : "+f"(d[0]), "+f"(d[1]), "+f"(d[2]), "+f"(d[3])
        : "r"(a[0]), "r"(a[1]), "r"(a[2]), "r"(a[3]), "r"(b0), "r"(b1));
}

// ---------------------------------------------------------------------------
// Weight prep: split all weights into bf16 hi/lo planes
// ---------------------------------------------------------------------------
__global__ void k_wprep(const float* __restrict__ fc0,
                        const float* __restrict__ w1,
                        const float* __restrict__ ws,
                        const float* __restrict__ fcc) {
    int t = blockIdx.x * blockDim.x + threadIdx.x;
    if (t >= WTOTAL) return;
    float v;
    if (t < 163840) {
        v = fc0[t];
    } else if (t < 409600) {
        int u = t - 163840;
        int k = u / 49152, r = u % 49152;
        int n = r / 384, c = r % 384;
        if (c < 128) v = w1[((size_t)k * HID + n) * 128 + c];
        else         v = ws[((size_t)k * HID + n) * 256 + (c - 128)];
    } else {
        v = fcc[t - 409600];
    }
    __nv_bfloat16 hi = __float2bfloat16(v);
    float lo = v - __bfloat162float(hi);
    g_wh[t] = hi;
    g_wl[t] = __float2bfloat16(lo);
}

// ---------------------------------------------------------------------------
// Zeroing
// ---------------------------------------------------------------------------
__global__ void k_zero_all() {   // bins0 + bins1 + cnt; grid 8192x256 (uint4)
    int t = blockIdx.x * blockDim.x + threadIdx.x;     // < 2097152
    uint4 z = make_uint4(0, 0, 0, 0);
    ((uint4*)g_bins0)[t] = z;
    ((uint4*)g_bins1)[t] = z;
    if (t < (BB * R2) / 4) ((uint4*)g_cnt)[t] = z;
}
__global__ void k_zero_b(unsigned* __restrict__ p) {   // grid 8192x256
    int t = blockIdx.x * blockDim.x + threadIdx.x;
    ((uint4*)p)[t] = make_uint4(0, 0, 0, 0);
}

// ---------------------------------------------------------------------------
// fc_pos + bin index + bin counts
// ---------------------------------------------------------------------------
__global__ void k_pos(const float* __restrict__ pts,
                      const float* __restrict__ w,
                      const float* __restrict__ b) {
    int m = blockIdx.x;
    int j = threadIdx.x;
    float p0 = pts[(size_t)m * 3 + 0];
    float p1 = pts[(size_t)m * 3 + 1];
    float p2 = pts[(size_t)m * 3 + 2];
    float v = b[j] + p0 * w[j * 3 + 0] + p1 * w[j * 3 + 1] + p2 * w[j * 3 + 2];
    g_XH[(size_t)m * LDXH + 128 + j] = v;
    if (j == 0) {
        int gx = (int)(p0 * (float)RESO);
        int gy = (int)(p1 * (float)RESO);
        gx = min(max(gx, 0), RESO - 1);
        gy = min(max(gy, 0), RESO - 1);
        int idx = gx + RESO * gy;
        g_idx[m] = idx;
        atomicAdd(&g_cnt[((m >> 14) << 14) + idx], 1.0f);
    }
}

// ---------------------------------------------------------------------------
// Fused pipelined mma.sync GEMM: C[M x 128] = act(A) @ W^T + bias
//  A chunks: c < nXHc from g_XH (col a_col0 + 32c, f32);
//            c >= nXHc gathered from binsSrc[(b,idx[row])] (f_enc u32).
//  reluAll: relu every A element (XH: fmax; bins: relu-decode).
//  mode 0: write relu(C+bias) -> XH col c_col0                (H, pre-relu'd)
//  mode 1: write C+bias -> XH col c_col0; if binsDst: scatter atomicMax(enc)
//  mode 2: scatter atomicAdd C+bias into (float*)binsDst      (fc_c)
// ---------------------------------------------------------------------------
__global__ void __launch_bounds__(256, 2) k_gemm_mma(
    int a_col0, size_t woff, int K, int reluAll,
    const float* __restrict__ bias, int c_col0, int mode,
    const unsigned* __restrict__ binsSrc, unsigned* __restrict__ binsDst,
    int nXHc)
{
    extern __shared__ char dsm[];
    uint32_t sbase = smem_u32(dsm);
    float* bias_s = (float*)(dsm + 2 * STG);

    int tid = threadIdx.x;
    int wid = tid >> 5;
    int lid = tid & 31;
    int m0  = blockIdx.x * 128;
    int batch = m0 >> 14;
    int warp_m = wid & 3;
    int warp_n = wid >> 2;
    int g  = lid >> 2;
    int tg = lid & 3;

    if (tid < 128) bias_s[tid] = bias[tid];

    // Producer sources: 4 A segments + 4 W segments, 16B each per chunk
    uint64_t gAx[4];            // XH path
    uint64_t gAb[4];            // bins path (valid if binsSrc)
    uint64_t gW[4];
    uint32_t sA[4], sW[4];
    {
        #pragma unroll
        for (int i = 0; i < 4; i++) {
            int idx = tid + (i << 8);
            int row = idx >> 3, seg = idx & 7;
            gAx[i] = (uint64_t)(g_XH + (size_t)(m0 + row) * LDXH + a_col0 + seg * 4);
            sA[i]  = row * 160 + seg * 16;
            if (binsSrc) {
                int bi = g_idx[m0 + row];
                gAb[i] = (uint64_t)(binsSrc + (((size_t)(batch << 14) + bi) << 7) + seg * 4);
            }
        }
        #pragma unroll
        for (int i = 0; i < 4; i++) {
            int idx = tid + (i << 8);
            int pl = idx >> 9, rem = idx & 511;
            int row = rem >> 2, seg = rem & 3;
            const __nv_bfloat16* gp = pl ? g_wl : g_wh;
            gW[i] = (uint64_t)(gp + woff + (size_t)row * K + seg * 8);
            sW[i] = 20480 + pl * 10240 + row * 80 + seg * 16;
        }
    }

    auto issue = [&](int c, int s) {
        uint32_t sb = sbase + s * STG;
        bool xh = (c < nXHc);
        uint64_t advA = (uint64_t)((xh ? c : (c - nXHc)) << 7);  // 128 B per chunk
        uint64_t advW = (uint64_t)(c << 6);                       // 64 B per chunk
        #pragma unroll
        for (int i = 0; i < 4; i++) {
            uint64_t src = (xh ? gAx[i] : gAb[i]) + advA;
            asm volatile("cp.async.cg.shared.global [%0], [%1], 16;"
                         :: "r"(sb + sA[i]), "l"(src) : "memory");
        }
        #pragma unroll
        for (int i = 0; i < 4; i++)
            asm volatile("cp.async.cg.shared.global [%0], [%1], 16;"
                         :: "r"(sb + sW[i]), "l"(gW[i] + advW) : "memory");
        asm volatile("cp.async.commit_group;" ::: "memory");
    };

    float acc[2][8][4];
    #pragma unroll
    for (int mt = 0; mt < 2; mt++)
        #pragma unroll
        for (int nt = 0; nt < 8; nt++)
            #pragma unroll
            for (int r = 0; r < 4; r++) acc[mt][nt][r] = 0.f;

    const int nchunks = K >> 5;
    issue(0, 0);

    for (int c = 0; c < nchunks; c++) {
        if (c + 1 < nchunks) {
            issue(c + 1, (c + 1) & 1);
            asm volatile("cp.async.wait_group 1;" ::: "memory");
        } else {
            asm volatile("cp.async.wait_group 0;" ::: "memory");
        }
        __syncthreads();

        const char* sp = dsm + (c & 1) * STG;
        const uint32_t* Au   = (const uint32_t*)sp;
        const uint32_t* W32h = (const uint32_t*)(sp + 20480);
        const uint32_t* W32l = (const uint32_t*)(sp + 30720);
        bool enc  = (c >= nXHc);
        bool relu = (reluAll != 0);

        #pragma unroll
        for (int ks = 0; ks < 2; ks++) {
            int col0 = (ks << 4) + (tg << 1);
            int kb   = (ks << 3) + tg;
            uint32_t ah[2][4], al[2][4];
            #pragma unroll
            for (int mt = 0; mt < 2; mt++) {
                int r0 = (warp_m << 5) + (mt << 4) + g;
                uint2 u0 = *(const uint2*)(Au + r0 * 40 + col0);
                uint2 u1 = *(const uint2*)(Au + (r0 + 8) * 40 + col0);
                uint2 u2 = *(const uint2*)(Au + r0 * 40 + col0 + 8);
                uint2 u3 = *(const uint2*)(Au + (r0 + 8) * 40 + col0 + 8);
                split2(cvtA(u0.x, enc, relu), cvtA(u0.y, enc, relu), ah[mt][0], al[mt][0]);
                split2(cvtA(u1.x, enc, relu), cvtA(u1.y, enc, relu), ah[mt][1], al[mt][1]);
                split2(cvtA(u2.x, enc, relu), cvtA(u2.y, enc, relu), ah[mt][2], al[mt][2]);
                split2(cvtA(u3.x, enc, relu), cvtA(u3.y, enc, relu), ah[mt][3], al[mt][3]);
            }
            #pragma unroll
            for (int nt = 0; nt < 8; nt++) {
                int n  = (warp_n << 6) + (nt << 3) + g;
                int bb = n * 20 + kb;
                uint32_t bh0 = W32h[bb], bh1 = W32h[bb + 4];
                uint32_t bl0 = W32l[bb], bl1 = W32l[bb + 4];
                #pragma unroll
                for (int mt = 0; mt < 2; mt++) {
                    mma16816(acc[mt][nt], ah[mt], bh0, bh1);
                    mma16816(acc[mt][nt], ah[mt], bl0, bl1);
                    mma16816(acc[mt][nt], al[mt], bh0, bh1);
                }
            }
        }
        __syncthreads();
    }

    // Epilogue rows: r_base + {0,8,16,24}
    int r_base = m0 + (warp_m << 5) + g;
    size_t bofs[4];
    if ((mode == 1 && binsDst) || mode == 2) {
        #pragma unroll
        for (int j = 0; j < 4; j++) {
            int bi = g_idx[r_base + 8 * j];
            bofs[j] = ((size_t)(batch << 14) + bi) << 7;
        }
    }

    #pragma unroll
    for (int mt = 0; mt < 2; mt++) {
        int row0 = r_base + (mt << 4);
        #pragma unroll
        for (int nt = 0; nt < 8; nt++) {
            int colL = (warp_n << 6) + (nt << 3) + (tg << 1);
            float b0 = bias_s[colL], b1 = bias_s[colL + 1];
            float v0 = acc[mt][nt][0] + b0, v1 = acc[mt][nt][1] + b1;  // row0
            float v2 = acc[mt][nt][2] + b0, v3 = acc[mt][nt][3] + b1;  // row0+8
            if (mode == 0) {
                v0 = fmaxf(v0, 0.f); v1 = fmaxf(v1, 0.f);
                v2 = fmaxf(v2, 0.f); v3 = fmaxf(v3, 0.f);
            }
            if (mode == 2) {
                float* sums = (float*)binsDst;
                atomicAdd(&sums[bofs[mt * 2 + 0] + colL],     v0);
                atomicAdd(&sums[bofs[mt * 2 + 0] + colL + 1], v1);
                atomicAdd(&sums[bofs[mt * 2 + 1] + colL],     v2);
                atomicAdd(&sums[bofs[mt * 2 + 1] + colL + 1], v3);
            } else {
                *(float2*)(g_XH + (size_t)row0 * LDXH + c_col0 + colL) =
                    make_float2(v0, v1);
                *(float2*)(g_XH + (size_t)(row0 + 8) * LDXH + c_col0 + colL) =
                    make_float2(v2, v3);
                if (mode == 1 && binsDst) {
                    atomicMax(&binsDst[bofs[mt * 2 + 0] + colL],     f_enc(v0));
                    atomicMax(&binsDst[bofs[mt * 2 + 0] + colL + 1], f_enc(v1));
                    atomicMax(&binsDst[bofs[mt * 2 + 1] + colL],     f_enc(v2));
                    atomicMax(&binsDst[bofs[mt * 2 + 1] + colL + 1], f_enc(v3));
                }
            }
        }
    }
}

// ---------------------------------------------------------------------------
// Final: mean + transposed plane write (sums = bins0 as float)
// ---------------------------------------------------------------------------
__global__ void k_final(float* __restrict__ out) {
    __shared__ float s[32][33];
    __shared__ float sc[32];
    int b    = blockIdx.z;
    int bin0 = blockIdx.x * 32;
    int c0   = blockIdx.y * 32;
    const float* sums = (const float*)g_bins0;

    #pragma unroll
    for (int i = 0; i < 4; i++) {
        int binl = threadIdx.y + i * 8;
        s[binl][threadIdx.x] =
            sums[((size_t)(b * R2 + bin0 + binl)) * HID + c0 + threadIdx.x];
    }
    if (threadIdx.y == 0)
        sc[threadIdx.x] = fmaxf(g_cnt[b * R2 + bin0 + threadIdx.x], 1.0f);
    __syncthreads();

    #pragma unroll
    for (int i = 0; i < 4; i++) {
        int c = c0 + threadIdx.y + i * 8;
        out[((size_t)(b * HID + c)) * R2 + bin0 + threadIdx.x] =
            s[threadIdx.x][threadIdx.y + i * 8] / sc[threadIdx.x];
    }
}

// ---------------------------------------------------------------------------
// Launch
// ---------------------------------------------------------------------------
extern "C" void kernel_launch(void* const* d_in, const int* in_sizes, int n_in,
                              void* d_out, int out_size) {
    const float* points    = (const float*)d_in[0];
    const float* fc_pos_w  = (const float*)d_in[1];
    const float* fc_pos_b  = (const float*)d_in[2];
    const float* blk_fc0_w = (const float*)d_in[3];
    const float* blk_fc0_b = (const float*)d_in[4];
    const float* blk_fc1_w = (const float*)d_in[5];
    const float* blk_fc1_b = (const float*)d_in[6];
    const float* blk_sc_w  = (const float*)d_in[7];
    const float* fc_c_w    = (const float*)d_in[8];
    const float* fc_c_b    = (const float*)d_in[9];
    float* out = (float*)d_out;

    const int GB      = MM / 128;      // 512 GEMM blocks
    const int SMEM_SZ = 2 * STG + 512; // 82432 B

    cudaFuncSetAttribute(k_gemm_mma, cudaFuncAttributeMaxDynamicSharedMemorySize, SMEM_SZ);

    unsigned* bins[2];
    cudaGetSymbolAddress((void**)&bins[0], g_bins0);
    cudaGetSymbolAddress((void**)&bins[1], g_bins1);

    k_wprep<<<(WTOTAL + 255) / 256, 256>>>(blk_fc0_w, blk_fc1_w, blk_sc_w, fc_c_w);
    k_zero_all<<<8192, 256>>>();
    k_pos<<<MM, 256>>>(points, fc_pos_w, fc_pos_b);

    // Block 0 (no gather): H = relu(relu(x)@W0+b0) -> col 0;
    // net = [reluH | x]@Wcat + b1 -> col 128, scatter-max -> bins0
    k_gemm_mma<<<GB, 256, SMEM_SZ>>>(128, WOFF_FC0(0), 256, 1, blk_fc0_b, 0, 0,
                                     nullptr, nullptr, 8);
    k_gemm_mma<<<GB, 256, SMEM_SZ>>>(0, WOFF_WCAT(0), 384, 0, blk_fc1_b, 128, 1,
                                     nullptr, bins[0], 12);

    // Blocks 1..4: gather pooled from src bins; GEMM2 scatters into dst bins
    for (int k = 1; k < NBLK; k++) {
        const unsigned* src = bins[(k + 1) & 1];   // k=1:bins0, k=2:bins1, ...
        unsigned* dst = (k < 4) ? bins[k & 1] : nullptr;
        k_gemm_mma<<<GB, 256, SMEM_SZ>>>(128, WOFF_FC0(k), 256, 1,
                                         blk_fc0_b + k * HID, 0, 0,
                                         src, nullptr, 4);
        k_gemm_mma<<<GB, 256, SMEM_SZ>>>(0, WOFF_WCAT(k), 384, 0,
                                         blk_fc1_b + k * HID, 128, 1,
                                         src, dst, 8);
        // re-arm the buffer GEMM2(k+1) will scatter into (last read just ended)
        if (k == 1) k_zero_b<<<8192, 256>>>(bins[0]);
        if (k == 2) k_zero_b<<<8192, 256>>>(bins[1]);
        if (k == 3) k_zero_b<<<8192, 256>>>(bins[0]);   // becomes sums buffer
    }

    // fc_c: relu(net)@fcc + b -> scatter-add into sums (= bins0)
    k_gemm_mma<<<GB, 256, SMEM_SZ>>>(128, WOFF_FCC, 128, 1, fc_c_b, 0, 2,
                                     nullptr, bins[0], 4);

    dim3 fgrid(R2 / 32, HID / 32, BB);
    dim3 fblk(32, 8);
    k_final<<<fgrid, fblk>>>(out);
}